// round 2
// baseline (speedup 1.0000x reference)
#include <cuda_runtime.h>
#include <cuda_bf16.h>

#define N_NODES 100000
#define N_EDGES 1600000
#define F_IN 128
#define N_H 3
#define N_D 16
#define HD 48
#define NEG_SLOPE 0.2f

// Scratch (device globals)
__device__ float  g_feat[N_NODES * HD];     // projected features (N,48)
__device__ float4 g_el[N_NODES];            // (el0,el1,el2,_)
__device__ float4 g_er[N_NODES];            // (er0,er1,er2,_)
__device__ float4 g_edge[N_EDGES];          // packed (src_as_float, x0, x1, x2), grouped by dst
__device__ int    g_count[N_NODES];         // in-degree
__device__ int    g_off[N_NODES];           // CSR segment start (exclusive scan)
__device__ int    g_cur[N_NODES];           // scatter cursor (mutable copy of g_off)

// ---------------------------------------------------------------------------
// Kernel 0: zero degree counters
// ---------------------------------------------------------------------------
__global__ void k_init() {
    int i = blockIdx.x * blockDim.x + threadIdx.x;
    if (i < N_NODES) g_count[i] = 0;
}

// ---------------------------------------------------------------------------
// Kernel 1: feat = x @ W^T  (N x 48), plus el/er attention logits.
// ---------------------------------------------------------------------------
__global__ __launch_bounds__(128) void k_gemm(const float* __restrict__ x,
                                              const float* __restrict__ W,
                                              const float* __restrict__ al,
                                              const float* __restrict__ ar)
{
    __shared__ float Ws[F_IN][HD];
    __shared__ float als[HD], ars[HD];
    for (int i = threadIdx.x; i < HD * F_IN; i += 128) {
        int j = i / F_IN, k = i % F_IN;
        Ws[k][j] = W[i];
    }
    if (threadIdx.x < HD) {
        als[threadIdx.x] = al[threadIdx.x];
        ars[threadIdx.x] = ar[threadIdx.x];
    }
    __syncthreads();

    int t  = blockIdx.x * 128 + threadIdx.x;
    int n0 = 2 * t, n1 = 2 * t + 1;
    if (n0 >= N_NODES) return;
    bool has1 = (n1 < N_NODES);

    float acc0[HD], acc1[HD];
#pragma unroll
    for (int j = 0; j < HD; j++) { acc0[j] = 0.f; acc1[j] = 0.f; }

    const float4* x4 = (const float4*)x;
    int b0 = n0 * (F_IN / 4);
    int b1 = n1 * (F_IN / 4);

    for (int i = 0; i < F_IN / 4; i++) {
        float4 a = x4[b0 + i];
        float4 b = has1 ? x4[b1 + i] : make_float4(0.f, 0.f, 0.f, 0.f);
#pragma unroll
        for (int j = 0; j < HD; j++) {
            float w0 = Ws[4 * i + 0][j];
            float w1 = Ws[4 * i + 1][j];
            float w2 = Ws[4 * i + 2][j];
            float w3 = Ws[4 * i + 3][j];
            acc0[j] = fmaf(a.x, w0, fmaf(a.y, w1, fmaf(a.z, w2, fmaf(a.w, w3, acc0[j]))));
            acc1[j] = fmaf(b.x, w0, fmaf(b.y, w1, fmaf(b.z, w2, fmaf(b.w, w3, acc1[j]))));
        }
    }

    {
        float el[N_H], er[N_H];
#pragma unroll
        for (int h = 0; h < N_H; h++) { el[h] = 0.f; er[h] = 0.f; }
#pragma unroll
        for (int h = 0; h < N_H; h++)
#pragma unroll
            for (int d = 0; d < N_D; d++) {
                el[h] = fmaf(acc0[h * N_D + d], als[h * N_D + d], el[h]);
                er[h] = fmaf(acc0[h * N_D + d], ars[h * N_D + d], er[h]);
            }
        g_el[n0] = make_float4(el[0], el[1], el[2], 0.f);
        g_er[n0] = make_float4(er[0], er[1], er[2], 0.f);
        float4* f4 = (float4*)(g_feat + (size_t)n0 * HD);
#pragma unroll
        for (int j = 0; j < HD / 4; j++)
            f4[j] = make_float4(acc0[4 * j], acc0[4 * j + 1], acc0[4 * j + 2], acc0[4 * j + 3]);
    }
    if (has1) {
        float el[N_H], er[N_H];
#pragma unroll
        for (int h = 0; h < N_H; h++) { el[h] = 0.f; er[h] = 0.f; }
#pragma unroll
        for (int h = 0; h < N_H; h++)
#pragma unroll
            for (int d = 0; d < N_D; d++) {
                el[h] = fmaf(acc1[h * N_D + d], als[h * N_D + d], el[h]);
                er[h] = fmaf(acc1[h * N_D + d], ars[h * N_D + d], er[h]);
            }
        g_el[n1] = make_float4(el[0], el[1], el[2], 0.f);
        g_er[n1] = make_float4(er[0], er[1], er[2], 0.f);
        float4* f4 = (float4*)(g_feat + (size_t)n1 * HD);
#pragma unroll
        for (int j = 0; j < HD / 4; j++)
            f4[j] = make_float4(acc1[4 * j], acc1[4 * j + 1], acc1[4 * j + 2], acc1[4 * j + 3]);
    }
}

// ---------------------------------------------------------------------------
// Kernel 2: in-degree histogram
// ---------------------------------------------------------------------------
__global__ void k_hist(const int* __restrict__ dst) {
    int e = blockIdx.x * blockDim.x + threadIdx.x;
    if (e >= N_EDGES) return;
    atomicAdd(&g_count[dst[e]], 1);
}

// ---------------------------------------------------------------------------
// Kernel 3: exclusive scan of g_count -> g_off, g_cur. One block, 1024 thr.
// ---------------------------------------------------------------------------
__global__ __launch_bounds__(1024) void k_scan() {
    __shared__ int ssum[1024];
    const int CH = (N_NODES + 1023) / 1024;  // 98
    int t = threadIdx.x;
    int beg = t * CH;
    int end = min(beg + CH, N_NODES);
    int s = 0;
    for (int i = beg; i < end; i++) s += g_count[i];
    ssum[t] = s;
    __syncthreads();
    // Hillis-Steele inclusive scan over 1024 partials
    for (int off = 1; off < 1024; off <<= 1) {
        int v = (t >= off) ? ssum[t - off] : 0;
        __syncthreads();
        ssum[t] += v;
        __syncthreads();
    }
    int excl = (t == 0) ? 0 : ssum[t - 1];
    for (int i = beg; i < end; i++) {
        int c = g_count[i];
        g_off[i] = excl;
        g_cur[i] = excl;
        excl += c;
    }
}

// ---------------------------------------------------------------------------
// Kernel 4: edge scatter — compute exp(leakyrelu(el[src]+er[dst])) per head,
// pack (src, x0, x1, x2) into the dst-grouped edge array.
// Max-subtraction skipped: |e| <= ~4, softmax is shift-invariant (fp32-safe).
// ---------------------------------------------------------------------------
__global__ void k_scatter(const int* __restrict__ src, const int* __restrict__ dst) {
    int e = blockIdx.x * blockDim.x + threadIdx.x;
    if (e >= N_EDGES) return;
    int s = src[e], d = dst[e];
    float4 L = g_el[s];
    float4 R = g_er[d];
    float v0 = L.x + R.x, v1 = L.y + R.y, v2 = L.z + R.z;
    v0 = v0 > 0.f ? v0 : NEG_SLOPE * v0;
    v1 = v1 > 0.f ? v1 : NEG_SLOPE * v1;
    v2 = v2 > 0.f ? v2 : NEG_SLOPE * v2;
    float x0 = __expf(v0), x1 = __expf(v1), x2 = __expf(v2);
    int pos = atomicAdd(&g_cur[d], 1);
    g_edge[pos] = make_float4(__int_as_float(s), x0, x1, x2);
}

// ---------------------------------------------------------------------------
// Kernel 5: per-dst aggregation. 48 threads per node (one per output comp),
// 4 nodes per 192-thread block. Pure loads, register accumulation, one store.
// Fuses softmax normalization and the linear_comb blend.
// ---------------------------------------------------------------------------
__global__ __launch_bounds__(192) void k_agg(const float* __restrict__ lin,
                                             float* __restrict__ out) {
    int d = blockIdx.x * 4 + threadIdx.y;
    if (d >= N_NODES) return;
    int c = threadIdx.x;        // 0..47
    int h = c >> 4;             // head index 0..2

    int beg = g_off[d];
    int cnt = g_count[d];
    int end = beg + cnt;

    float num = 0.f, den = 0.f;
#pragma unroll 2
    for (int p = beg; p < end; p++) {
        float4 pk = g_edge[p];
        int s = __float_as_int(pk.x);
        float a = (h == 0) ? pk.y : ((h == 1) ? pk.z : pk.w);
        float f = __ldg(&g_feat[s * HD + c]);
        num = fmaf(a, f, num);
        den += a;
    }
    float msg = (cnt > 0) ? (num / den) : 0.f;
    float l = lin[d];
    float fd = g_feat[d * HD + c];
    out[d * HD + c] = (1.f - l) * msg + l * fd;
}

// ---------------------------------------------------------------------------
extern "C" void kernel_launch(void* const* d_in, const int* in_sizes, int n_in,
                              void* d_out, int out_size) {
    const float* x   = (const float*)d_in[0];
    const float* W   = (const float*)d_in[1];
    const float* al  = (const float*)d_in[2];
    const float* ar  = (const float*)d_in[3];
    const float* lin = (const float*)d_in[4];
    const int*   src = (const int*)d_in[5];
    const int*   dst = (const int*)d_in[6];
    float* out = (float*)d_out;

    k_init<<<(N_NODES + 255) / 256, 256>>>();
    k_gemm<<<(N_NODES + 255) / 256, 128>>>(x, W, al, ar);
    k_hist<<<(N_EDGES + 255) / 256, 256>>>(dst);
    k_scan<<<1, 1024>>>();
    k_scatter<<<(N_EDGES + 255) / 256, 256>>>(src, dst);

    dim3 aggBlock(48, 4);
    k_agg<<<(N_NODES + 3) / 4, aggBlock>>>(lin, out);
}

// round 3
// speedup vs baseline: 1.7405x; 1.7405x over previous
#include <cuda_runtime.h>
#include <cuda_bf16.h>

#define N_NODES 100000
#define N_EDGES 1600000
#define F_IN 128
#define N_H 3
#define N_D 16
#define HD 48
#define NEG_SLOPE 0.2f

#define SCAN_B 256
#define NB ((N_NODES + SCAN_B - 1) / SCAN_B)   // 391

// Scratch (device globals)
__device__ float  g_feat[N_NODES * HD];     // projected features (N,48)
__device__ float4 g_el[N_NODES];            // (el0,el1,el2,_)
__device__ float4 g_er[N_NODES];            // (er0,er1,er2,_)
__device__ float4 g_edge[N_EDGES];          // packed (src_as_float, x0, x1, x2), grouped by dst
__device__ int    g_count[N_NODES];         // in-degree
__device__ int    g_off[N_NODES];           // CSR segment start (exclusive scan)
__device__ int    g_cur[N_NODES];           // scatter cursor
__device__ int    g_bsum[NB];               // per-block count sums
__device__ int    g_bbase[NB];              // exclusive scan of block sums

// ---------------------------------------------------------------------------
// Kernel 0: zero degree counters
// ---------------------------------------------------------------------------
__global__ void k_init() {
    int i = blockIdx.x * blockDim.x + threadIdx.x;
    if (i < N_NODES) g_count[i] = 0;
}

// ---------------------------------------------------------------------------
// Kernel 1: feat = x @ W^T  (N x 48), plus el/er attention logits.
// ---------------------------------------------------------------------------
__global__ __launch_bounds__(128) void k_gemm(const float* __restrict__ x,
                                              const float* __restrict__ W,
                                              const float* __restrict__ al,
                                              const float* __restrict__ ar)
{
    __shared__ float Ws[F_IN][HD];
    __shared__ float als[HD], ars[HD];
    for (int i = threadIdx.x; i < HD * F_IN; i += 128) {
        int j = i / F_IN, k = i % F_IN;
        Ws[k][j] = W[i];
    }
    if (threadIdx.x < HD) {
        als[threadIdx.x] = al[threadIdx.x];
        ars[threadIdx.x] = ar[threadIdx.x];
    }
    __syncthreads();

    int t  = blockIdx.x * 128 + threadIdx.x;
    int n0 = 2 * t, n1 = 2 * t + 1;
    if (n0 >= N_NODES) return;
    bool has1 = (n1 < N_NODES);

    float acc0[HD], acc1[HD];
#pragma unroll
    for (int j = 0; j < HD; j++) { acc0[j] = 0.f; acc1[j] = 0.f; }

    const float4* x4 = (const float4*)x;
    int b0 = n0 * (F_IN / 4);
    int b1 = n1 * (F_IN / 4);

    for (int i = 0; i < F_IN / 4; i++) {
        float4 a = x4[b0 + i];
        float4 b = has1 ? x4[b1 + i] : make_float4(0.f, 0.f, 0.f, 0.f);
#pragma unroll
        for (int j = 0; j < HD; j++) {
            float w0 = Ws[4 * i + 0][j];
            float w1 = Ws[4 * i + 1][j];
            float w2 = Ws[4 * i + 2][j];
            float w3 = Ws[4 * i + 3][j];
            acc0[j] = fmaf(a.x, w0, fmaf(a.y, w1, fmaf(a.z, w2, fmaf(a.w, w3, acc0[j]))));
            acc1[j] = fmaf(b.x, w0, fmaf(b.y, w1, fmaf(b.z, w2, fmaf(b.w, w3, acc1[j]))));
        }
    }

    {
        float el[N_H], er[N_H];
#pragma unroll
        for (int h = 0; h < N_H; h++) { el[h] = 0.f; er[h] = 0.f; }
#pragma unroll
        for (int h = 0; h < N_H; h++)
#pragma unroll
            for (int d = 0; d < N_D; d++) {
                el[h] = fmaf(acc0[h * N_D + d], als[h * N_D + d], el[h]);
                er[h] = fmaf(acc0[h * N_D + d], ars[h * N_D + d], er[h]);
            }
        g_el[n0] = make_float4(el[0], el[1], el[2], 0.f);
        g_er[n0] = make_float4(er[0], er[1], er[2], 0.f);
        float4* f4 = (float4*)(g_feat + (size_t)n0 * HD);
#pragma unroll
        for (int j = 0; j < HD / 4; j++)
            f4[j] = make_float4(acc0[4 * j], acc0[4 * j + 1], acc0[4 * j + 2], acc0[4 * j + 3]);
    }
    if (has1) {
        float el[N_H], er[N_H];
#pragma unroll
        for (int h = 0; h < N_H; h++) { el[h] = 0.f; er[h] = 0.f; }
#pragma unroll
        for (int h = 0; h < N_H; h++)
#pragma unroll
            for (int d = 0; d < N_D; d++) {
                el[h] = fmaf(acc1[h * N_D + d], als[h * N_D + d], el[h]);
                er[h] = fmaf(acc1[h * N_D + d], ars[h * N_D + d], er[h]);
            }
        g_el[n1] = make_float4(el[0], el[1], el[2], 0.f);
        g_er[n1] = make_float4(er[0], er[1], er[2], 0.f);
        float4* f4 = (float4*)(g_feat + (size_t)n1 * HD);
#pragma unroll
        for (int j = 0; j < HD / 4; j++)
            f4[j] = make_float4(acc1[4 * j], acc1[4 * j + 1], acc1[4 * j + 2], acc1[4 * j + 3]);
    }
}

// ---------------------------------------------------------------------------
// Kernel 2: in-degree histogram
// ---------------------------------------------------------------------------
__global__ void k_hist(const int* __restrict__ dst) {
    int e = blockIdx.x * blockDim.x + threadIdx.x;
    if (e >= N_EDGES) return;
    atomicAdd(&g_count[dst[e]], 1);
}

// ---------------------------------------------------------------------------
// Kernel 3a: per-block sums of g_count
// ---------------------------------------------------------------------------
__global__ __launch_bounds__(SCAN_B) void k_bsum() {
    __shared__ int sh[SCAN_B];
    int i = blockIdx.x * SCAN_B + threadIdx.x;
    sh[threadIdx.x] = (i < N_NODES) ? g_count[i] : 0;
    __syncthreads();
    for (int off = SCAN_B / 2; off > 0; off >>= 1) {
        if (threadIdx.x < off) sh[threadIdx.x] += sh[threadIdx.x + off];
        __syncthreads();
    }
    if (threadIdx.x == 0) g_bsum[blockIdx.x] = sh[0];
}

// ---------------------------------------------------------------------------
// Kernel 3b: exclusive scan of 391 block sums (single small block)
// ---------------------------------------------------------------------------
__global__ __launch_bounds__(512) void k_sscan() {
    __shared__ int sh[512];
    int t = threadIdx.x;
    sh[t] = (t < NB) ? g_bsum[t] : 0;
    __syncthreads();
    for (int off = 1; off < 512; off <<= 1) {
        int v = (t >= off) ? sh[t - off] : 0;
        __syncthreads();
        sh[t] += v;
        __syncthreads();
    }
    if (t < NB) g_bbase[t] = (t == 0) ? 0 : sh[t - 1];
}

// ---------------------------------------------------------------------------
// Kernel 3c: in-block exclusive scan of counts + block base -> g_off, g_cur
// ---------------------------------------------------------------------------
__global__ __launch_bounds__(SCAN_B) void k_off() {
    __shared__ int sh[SCAN_B];
    int i = blockIdx.x * SCAN_B + threadIdx.x;
    int t = threadIdx.x;
    int c = (i < N_NODES) ? g_count[i] : 0;
    sh[t] = c;
    __syncthreads();
    for (int off = 1; off < SCAN_B; off <<= 1) {
        int v = (t >= off) ? sh[t - off] : 0;
        __syncthreads();
        sh[t] += v;
        __syncthreads();
    }
    if (i < N_NODES) {
        int excl = g_bbase[blockIdx.x] + sh[t] - c;  // inclusive - self = exclusive
        g_off[i] = excl;
        g_cur[i] = excl;
    }
}

// ---------------------------------------------------------------------------
// Kernel 4: edge scatter — exp(leakyrelu(el[src]+er[dst])) per head,
// pack (src, x0, x1, x2) into the dst-grouped edge array.
// Max-subtraction skipped: |e| <= ~4, softmax is shift-invariant (fp32-safe).
// ---------------------------------------------------------------------------
__global__ void k_scatter(const int* __restrict__ src, const int* __restrict__ dst) {
    int e = blockIdx.x * blockDim.x + threadIdx.x;
    if (e >= N_EDGES) return;
    int s = src[e], d = dst[e];
    float4 L = g_el[s];
    float4 R = g_er[d];
    float v0 = L.x + R.x, v1 = L.y + R.y, v2 = L.z + R.z;
    v0 = v0 > 0.f ? v0 : NEG_SLOPE * v0;
    v1 = v1 > 0.f ? v1 : NEG_SLOPE * v1;
    v2 = v2 > 0.f ? v2 : NEG_SLOPE * v2;
    float x0 = __expf(v0), x1 = __expf(v1), x2 = __expf(v2);
    int pos = atomicAdd(&g_cur[d], 1);
    g_edge[pos] = make_float4(__int_as_float(s), x0, x1, x2);
}

// ---------------------------------------------------------------------------
// Kernel 5: per-dst aggregation. 48 threads per node (one per output comp),
// register accumulation, fused softmax-normalize + linear_comb blend.
// ---------------------------------------------------------------------------
__global__ __launch_bounds__(192) void k_agg(const float* __restrict__ lin,
                                             float* __restrict__ out) {
    int d = blockIdx.x * 4 + threadIdx.y;
    if (d >= N_NODES) return;
    int c = threadIdx.x;        // 0..47
    int h = c >> 4;             // head index 0..2

    int beg = g_off[d];
    int cnt = g_count[d];
    int end = beg + cnt;

    float num = 0.f, den = 0.f;
#pragma unroll 2
    for (int p = beg; p < end; p++) {
        float4 pk = g_edge[p];
        int s = __float_as_int(pk.x);
        float a = (h == 0) ? pk.y : ((h == 1) ? pk.z : pk.w);
        float f = __ldg(&g_feat[s * HD + c]);
        num = fmaf(a, f, num);
        den += a;
    }
    float msg = (cnt > 0) ? (num / den) : 0.f;
    float l = lin[d];
    float fd = g_feat[d * HD + c];
    out[d * HD + c] = (1.f - l) * msg + l * fd;
}

// ---------------------------------------------------------------------------
extern "C" void kernel_launch(void* const* d_in, const int* in_sizes, int n_in,
                              void* d_out, int out_size) {
    const float* x   = (const float*)d_in[0];
    const float* W   = (const float*)d_in[1];
    const float* al  = (const float*)d_in[2];
    const float* ar  = (const float*)d_in[3];
    const float* lin = (const float*)d_in[4];
    const int*   src = (const int*)d_in[5];
    const int*   dst = (const int*)d_in[6];
    float* out = (float*)d_out;

    k_init<<<(N_NODES + 255) / 256, 256>>>();
    k_gemm<<<(N_NODES + 255) / 256, 128>>>(x, W, al, ar);
    k_hist<<<(N_EDGES + 255) / 256, 256>>>(dst);
    k_bsum<<<NB, SCAN_B>>>();
    k_sscan<<<1, 512>>>();
    k_off<<<NB, SCAN_B>>>();
    k_scatter<<<(N_EDGES + 255) / 256, 256>>>(src, dst);

    dim3 aggBlock(48, 4);
    k_agg<<<(N_NODES + 3) / 4, aggBlock>>>(lin, out);
}